// round 16
// baseline (speedup 1.0000x reference)
#include <cuda_runtime.h>
#include <cuda_fp16.h>
#include <cstdint>

#define HIDDEN 4096
#define INTER  14336
#define PREDH  1024
#define SEQ    4096
#define HC     716
#define NPAD   1536   // interleaved gate/up rows, padded
#define KPAD   768    // t / Wd storage stride
#define KDOWN  736    // down-GEMM K loop bound (= 23*32; cols 716..735 are exact zeros)
#define NBINS  4096

// ---------------- device scratch ----------------
__device__ __align__(256) float    g_p[PREDH];
__device__ __align__(256) unsigned g_key[INTER];
__device__ int g_hist[NBINS];
__device__ int g_cnt[4];
__device__ int g_sel[2];
__device__ __align__(256) int g_idx[HC];
__device__ int      g_cand_idx[INTER];
__device__ unsigned g_cand_key[INTER];
__device__ __align__(1024) __half g_xr[(size_t)SEQ * HIDDEN];   // x, f16, k-permuted
__device__ __align__(1024) __half g_b1[(size_t)NPAD * HIDDEN];  // interleaved Wg/Wu, f16, permuted
__device__ __align__(1024) __half g_wd[(size_t)HIDDEN * KPAD];  // gathered Wd, f16, permuted
__device__ __align__(1024) __half g_t [(size_t)SEQ * KPAD];     // silu(g)*u, f16, permuted

// ---------------- helpers ----------------
__device__ __forceinline__ unsigned smem_u32(const void* p) {
    return (unsigned)__cvta_generic_to_shared(p);
}
__device__ __forceinline__ void cp16(unsigned dst, const void* src) {
    asm volatile("cp.async.cg.shared.global [%0], [%1], 16;" :: "r"(dst), "l"(src) : "memory");
}
__device__ __forceinline__ void mmaf16(float* d, unsigned a0, unsigned a1, unsigned a2,
                                       unsigned a3, unsigned b0, unsigned b1) {
    asm volatile(
        "mma.sync.aligned.m16n8k16.row.col.f32.f16.f16.f32 "
        "{%0,%1,%2,%3}, {%4,%5,%6,%7}, {%8,%9}, {%0,%1,%2,%3};\n"
        : "+f"(d[0]), "+f"(d[1]), "+f"(d[2]), "+f"(d[3])
        : "r"(a0), "r"(a1), "r"(a2), "r"(a3), "r"(b0), "r"(b1));
}

// P32 permutation: within each 32-k block, pos = c*8 + b*4 + hi*2 + lo
// where k = 16*b + 8*hi + 2*c + lo.
__device__ __forceinline__ void perm_store32(const float* v, __half* dst) {
#pragma unroll
    for (int pos = 0; pos < 32; pos += 2) {
        int c = pos >> 3, b = (pos >> 2) & 1, hi = (pos >> 1) & 1;
        int k0 = 16 * b + 8 * hi + 2 * c;
        *(__half2*)(dst + pos) = __floats2half2_rn(v[k0], v[k0 + 1]);
    }
}

// ---------------- predictor (init fused) ----------------
__global__ void k_pred1(const float* __restrict__ x, const float* __restrict__ W1) {
    int gid = blockIdx.x * blockDim.x + threadIdx.x;
    if (gid < NBINS) g_hist[gid] = 0;
    if (gid < 4) g_cnt[gid] = 0;
    const float* xl = x + (size_t)(SEQ - 1) * HIDDEN;
    int warp = gid >> 5;
    int lane = threadIdx.x & 31;
    if (warp >= PREDH) return;
    const float* w = W1 + (size_t)warp * HIDDEN;
    double s = 0.0;
    for (int k = lane; k < HIDDEN; k += 32) s += (double)w[k] * (double)xl[k];
    for (int o = 16; o; o >>= 1) s += __shfl_down_sync(0xffffffffu, s, o);
    if (lane == 0) g_p[warp] = (float)s;
}
__global__ void k_pred2(const float* __restrict__ W2) {
    int warp = (blockIdx.x * blockDim.x + threadIdx.x) >> 5;
    int lane = threadIdx.x & 31;
    if (warp >= INTER) return;
    const float* w = W2 + (size_t)warp * PREDH;
    double s = 0.0;
    for (int k = lane; k < PREDH; k += 32) s += (double)w[k] * (double)g_p[k];
    for (int o = 16; o; o >>= 1) s += __shfl_down_sync(0xffffffffu, s, o);
    if (lane == 0) {
        float v = (float)s;
        unsigned u = __float_as_uint(v);
        u = (u & 0x80000000u) ? ~u : (u | 0x80000000u);
        g_key[warp] = u;
        atomicAdd(&g_hist[u >> 20], 1);
    }
}

// ---------------- threshold bin (1 block) ----------------
__global__ void k_thresh() {
    __shared__ int s4[1024];
    __shared__ int gsum[32];
    __shared__ int gabove[32];
    int t = threadIdx.x;
    s4[t] = g_hist[4*t] + g_hist[4*t+1] + g_hist[4*t+2] + g_hist[4*t+3];
    __syncthreads();
    if (t < 32) {
        int s = 0;
        for (int j = 0; j < 32; ++j) s += s4[t * 32 + j];
        gsum[t] = s;
    }
    __syncthreads();
    if (t == 0) {
        int acc = 0;
        for (int g = 31; g >= 0; --g) { gabove[g] = acc; acc += gsum[g]; }
        int g = 31;
        while (gabove[g] + gsum[g] < HC) --g;
        acc = gabove[g];
        for (int c = 31; c >= 0; --c) {
            int cell = g * 32 + c;
            int sc = s4[cell];
            if (acc + sc >= HC) {
                for (int bb = 3; bb >= 0; --bb) {
                    int h = g_hist[cell * 4 + bb];
                    if (acc + h >= HC) { g_sel[0] = cell * 4 + bb; g_sel[1] = acc; return; }
                    acc += h;
                }
            }
            acc += sc;
        }
    }
}
// ---------------- collect (multi-block, parallel scan of keys) -------------
__global__ void k_collect() {
    int i = blockIdx.x * blockDim.x + threadIdx.x;
    if (i >= INTER) return;
    unsigned key = g_key[i];
    int bin = g_sel[0];
    int b = (int)(key >> 20);
    if (b > bin) {
        int p = atomicAdd(&g_cnt[0], 1);
        g_idx[p] = i;
    } else if (b == bin) {
        int p = atomicAdd(&g_cnt[1], 1);
        g_cand_idx[p] = i;
        g_cand_key[p] = key;
    }
}
// ---------------- rank boundary bin (1 block) ----------------
__global__ void k_rank() {
    __shared__ unsigned sk[4096];
    __shared__ int      si[4096];
    int t = threadIdx.x;
    int m = g_cnt[1];
    int above = g_sel[1];
    int need = HC - above;
    bool use_s = (m <= 4096);
    if (use_s)
        for (int i = t; i < m; i += 512) { sk[i] = g_cand_key[i]; si[i] = g_cand_idx[i]; }
    __syncthreads();
    for (int j = t; j < m; j += 512) {
        unsigned kj = use_s ? sk[j] : g_cand_key[j];
        int ij      = use_s ? si[j] : g_cand_idx[j];
        int r = 0;
        for (int l = 0; l < m; ++l) {
            unsigned kl = use_s ? sk[l] : g_cand_key[l];
            int il      = use_s ? si[l] : g_cand_idx[l];
            r += (int)((kl > kj) || (kl == kj && il < ij));
        }
        if (r < need) g_idx[above + r] = ij;
    }
}

// ---------------- staging ----------------
__global__ void k_round_x(const float* __restrict__ x) {
    int nb = SEQ * HIDDEN / 32;
    for (int b = blockIdx.x * blockDim.x + threadIdx.x; b < nb; b += gridDim.x * blockDim.x) {
        float v[32];
        const float4* s = (const float4*)(x + (size_t)b * 32);
#pragma unroll
        for (int q = 0; q < 8; ++q) {
            float4 f = s[q];
            v[q*4] = f.x; v[q*4+1] = f.y; v[q*4+2] = f.z; v[q*4+3] = f.w;
        }
        perm_store32(v, g_xr + (size_t)b * 32);
    }
}
// blocks [0,NPAD): interleaved Wg/Wu row gather.  blocks [NPAD, NPAD+HIDDEN): Wd gather.
__global__ void k_gatherBW(const float* __restrict__ Wg, const float* __restrict__ Wu,
                           const float* __restrict__ Wd) {
    int bid = blockIdx.x;
    int t = threadIdx.x;
    if (bid < NPAD) {
        int k = bid >> 1;
        __half* dst = g_b1 + (size_t)bid * HIDDEN;
        if (k < HC) {
            const float* src = ((bid & 1) ? Wu : Wg) + (size_t)__ldg(&g_idx[k]) * HIDDEN;
            float v[32];
            const float4* s = (const float4*)(src + t * 32);
#pragma unroll
            for (int q = 0; q < 8; ++q) {
                float4 f = s[q];
                v[q*4] = f.x; v[q*4+1] = f.y; v[q*4+2] = f.z; v[q*4+3] = f.w;
            }
            perm_store32(v, dst + t * 32);
        } else {
            uint4* d4 = (uint4*)dst;
            for (int j = t * 4; j < (int)(HIDDEN * 2 / 16); j += 512) {
                d4[j] = make_uint4(0,0,0,0); d4[j+1] = make_uint4(0,0,0,0);
                d4[j+2] = make_uint4(0,0,0,0); d4[j+3] = make_uint4(0,0,0,0);
            }
        }
    } else {
        int h = bid - NPAD;
        if (t >= KPAD / 32) return;
        const float* row = Wd + (size_t)h * INTER;
        float v[32];
#pragma unroll
        for (int j = 0; j < 32; ++j) {
            int k = t * 32 + j;
            v[j] = (k < HC) ? __ldg(row + __ldg(&g_idx[k])) : 0.f;
        }
        perm_store32(v, g_wd + (size_t)h * KPAD + t * 32);
    }
}

// ---------------- GEMM1: fused gate/up, BM=128 BN=64, 128 thr, 4 CTAs/SM ----
// Warp tile 64x32 (proven). Grid 24x32 = 768 fine-grained CTAs -> smooth tail.
// t = f16(silu(g)*u) into P32 layout. Same accumulation order as before.
#define S1STAGES 4
#define S1H      6144    // halves per stage: A 4096 + B 2048 (12 KB)

__global__ void __launch_bounds__(128, 4) k_gemm1(
    const __half* __restrict__ A, const __half* __restrict__ B,
    __half* __restrict__ Ct)
{
    extern __shared__ __half dsm[];
    unsigned smb = smem_u32(dsm);

    int tid = threadIdx.x;
    int lane = tid & 31;
    int warp = tid >> 5;
    int wm = warp >> 1;   // 0..1 (64-row slab)
    int wn = warp & 1;    // 0..1 (32-col slab)
    int bm = blockIdx.y * 128;
    int bn = blockIdx.x * 64;

    // cp.async: A row tid (64B = 4 cp16); B row tid>>1, 32B part tid&1 (2 cp16)
    const __half* asrc = A + (size_t)(bm + tid) * HIDDEN;
    const __half* bsrc = B + (size_t)(bn + (tid >> 1)) * HIDDEN + (tid & 1) * 16;
    unsigned aoff = (unsigned)tid * 64u;
    unsigned boff = 8192u + (unsigned)((tid >> 1) * 64 + (tid & 1) * 32);

    float acc[4][4][4];
#pragma unroll
    for (int i = 0; i < 4; i++)
#pragma unroll
        for (int j = 0; j < 4; j++)
#pragma unroll
            for (int q = 0; q < 4; q++) acc[i][j][q] = 0.f;

    const int NT = HIDDEN / 32;
    auto load = [&](int kt) {
        unsigned base = smb + (unsigned)(kt & (S1STAGES - 1)) * (S1H * 2u);
        int k0 = kt * 32;
        cp16(base + aoff,        asrc + k0);
        cp16(base + aoff + 16u,  asrc + k0 + 8);
        cp16(base + aoff + 32u,  asrc + k0 + 16);
        cp16(base + aoff + 48u,  asrc + k0 + 24);
        cp16(base + boff,        bsrc + k0);
        cp16(base + boff + 16u,  bsrc + k0 + 8);
        asm volatile("cp.async.commit_group;" ::: "memory");
    };

    load(0);
    load(1);
    load(2);

    int r4 = lane >> 2, c4 = lane & 3;

    for (int kt = 0; kt < NT; ++kt) {
        if (kt + 3 < NT) load(kt + 3);
        int rem = NT - 1 - kt;
        if (rem >= 3)      asm volatile("cp.async.wait_group 3;" ::: "memory");
        else if (rem == 2) asm volatile("cp.async.wait_group 2;" ::: "memory");
        else if (rem == 1) asm volatile("cp.async.wait_group 1;" ::: "memory");
        else               asm volatile("cp.async.wait_group 0;" ::: "memory");
        __syncthreads();

        const uint4* as = (const uint4*)(dsm + (size_t)(kt & (S1STAGES - 1)) * S1H);
        const uint4* bs = as + 512;   // B half at +8192 bytes = +512 uint4

        uint4 vb[4];
#pragma unroll
        for (int ni = 0; ni < 4; ++ni)
            vb[ni] = bs[(wn * 32 + ni * 8 + r4) * 4 + c4];

#pragma unroll
        for (int mi = 0; mi < 4; ++mi) {
            int rbase = wm * 64 + mi * 16 + r4;
            uint4 va0 = as[rbase * 4 + c4];
            uint4 va1 = as[(rbase + 8) * 4 + c4];
#pragma unroll
            for (int ni = 0; ni < 4; ++ni) {
                mmaf16(acc[mi][ni], va0.x, va1.x, va0.y, va1.y, vb[ni].x, vb[ni].y);
                mmaf16(acc[mi][ni], va0.z, va1.z, va0.w, va1.w, vb[ni].z, vb[ni].w);
            }
        }
        __syncthreads();
    }

    // epilogue: 32 t-cols per tile (even N col = gate, odd = up), P32 layout.
    // warp wn covers t cols [wn*16, wn*16+16): q = ni*4+c4, j = wn*16+q,
    // pos = ((q>>1)&3)*8 + wn*4 + ((q>>3)&1)*2 + (q&1).
    {
        __half* ts = dsm;
        const int TST = 40;
#pragma unroll
        for (int mi = 0; mi < 4; ++mi) {
            int rl = wm * 64 + mi * 16 + r4;
#pragma unroll
            for (int ni = 0; ni < 4; ++ni) {
                int q = ni * 4 + c4;
                int pos = ((q >> 1) & 3) * 8 + wn * 4 + ((q >> 3) & 1) * 2 + (q & 1);
                float g0 = acc[mi][ni][0], u0 = acc[mi][ni][1];
                float g1 = acc[mi][ni][2], u1 = acc[mi][ni][3];
                ts[rl * TST + pos]       = __float2half(u0 * g0 / (1.f + __expf(-g0)));
                ts[(rl + 8) * TST + pos] = __float2half(u1 * g1 / (1.f + __expf(-g1)));
            }
        }
        __syncthreads();
        // coalesced copy: 128 rows x 32 halves (64B)
        const uint4* src = (const uint4*)(ts + tid * TST);
        uint4* dst = (uint4*)(Ct + (size_t)(bm + tid) * KPAD + (bn >> 1));
#pragma unroll
        for (int c = 0; c < 4; ++c) dst[c] = src[c];
    }
}

// ---------------- GEMM2 (down, byte-exact R15): 256 thr, 64x32 warp tile ---
#define STAGES 4
#define STG_H  8192            // halves per stage: A 4096 + B 4096 (16 KB)

__global__ void __launch_bounds__(256, 2) k_gemm2(
    const __half* __restrict__ A, const __half* __restrict__ B,
    float* __restrict__ C, int K, int lda, int ldb, int ldc)
{
    extern __shared__ __half dsm[];
    unsigned smb = smem_u32(dsm);

    int tid = threadIdx.x;
    int lane = tid & 31;
    int warp = tid >> 5;
    int wm = warp >> 2;   // 0..1
    int wn = warp & 3;    // 0..3
    int bm = blockIdx.y * 128;
    int bn = blockIdx.x * 128;

    int lrow = tid >> 1;
    int lpart = tid & 1;
    const __half* asrc = A + (size_t)(bm + lrow) * lda + lpart * 16;
    const __half* bsrc = B + (size_t)(bn + lrow) * ldb + lpart * 16;
    unsigned aoff = (unsigned)(lrow * 64 + lpart * 32);
    unsigned boff = 8192u + aoff;

    float acc[4][4][4];
#pragma unroll
    for (int i = 0; i < 4; i++)
#pragma unroll
        for (int j = 0; j < 4; j++)
#pragma unroll
            for (int q = 0; q < 4; q++) acc[i][j][q] = 0.f;

    int NT = K / 32;
    auto load = [&](int kt) {
        unsigned base = smb + (unsigned)(kt & (STAGES - 1)) * (STG_H * 2u);
        int k0 = kt * 32;
        cp16(base + aoff,       asrc + k0);
        cp16(base + aoff + 16u, asrc + k0 + 8);
        cp16(base + boff,       bsrc + k0);
        cp16(base + boff + 16u, bsrc + k0 + 8);
        asm volatile("cp.async.commit_group;" ::: "memory");
    };

    load(0);
    if (NT > 1) load(1);
    if (NT > 2) load(2);

    int r4 = lane >> 2, c4 = lane & 3;

    for (int kt = 0; kt < NT; ++kt) {
        if (kt + 3 < NT) load(kt + 3);
        int rem = NT - 1 - kt;
        if (rem >= 3)      asm volatile("cp.async.wait_group 3;" ::: "memory");
        else if (rem == 2) asm volatile("cp.async.wait_group 2;" ::: "memory");
        else if (rem == 1) asm volatile("cp.async.wait_group 1;" ::: "memory");
        else               asm volatile("cp.async.wait_group 0;" ::: "memory");
        __syncthreads();

        const uint4* as = (const uint4*)(dsm + (size_t)(kt & (STAGES - 1)) * STG_H);
        const uint4* bs = as + 512;

        uint4 vb[4];
#pragma unroll
        for (int ni = 0; ni < 4; ++ni)
            vb[ni] = bs[(wn * 32 + ni * 8 + r4) * 4 + c4];

#pragma unroll
        for (int mi = 0; mi < 4; ++mi) {
            int rbase = wm * 64 + mi * 16 + r4;
            uint4 va0 = as[rbase * 4 + c4];
            uint4 va1 = as[(rbase + 8) * 4 + c4];
#pragma unroll
            for (int ni = 0; ni < 4; ++ni) {
                mmaf16(acc[mi][ni], va0.x, va1.x, va0.y, va1.y, vb[ni].x, vb[ni].y);
                mmaf16(acc[mi][ni], va0.z, va1.z, va0.w, va1.w, vb[ni].z, vb[ni].w);
            }
        }
        __syncthreads();
    }

#pragma unroll
    for (int mi = 0; mi < 4; ++mi) {
        int r0 = bm + wm * 64 + mi * 16 + r4;
#pragma unroll
        for (int ni = 0; ni < 4; ++ni) {
            int cc = bn + wn * 32 + ni * 8 + c4 * 2;
            *(float2*)&C[(size_t)r0 * ldc + cc] =
                make_float2(acc[mi][ni][0], acc[mi][ni][1]);
            *(float2*)&C[(size_t)(r0 + 8) * ldc + cc] =
                make_float2(acc[mi][ni][2], acc[mi][ni][3]);
        }
    }
}

// ---------------- launch (single stream, fully sequential) ----------------
extern "C" void kernel_launch(void* const* d_in, const int* in_sizes, int n_in,
                              void* d_out, int out_size) {
    (void)in_sizes; (void)n_in; (void)out_size;
    const float* x  = (const float*)d_in[0];
    const float* Wg = (const float*)d_in[1];
    const float* Wu = (const float*)d_in[2];
    const float* Wd = (const float*)d_in[3];
    const float* W1 = (const float*)d_in[4];
    const float* W2 = (const float*)d_in[5];
    float* out = (float*)d_out;

    __half *pxr = nullptr, *pb1 = nullptr, *pwd = nullptr, *pt = nullptr;
    cudaGetSymbolAddress((void**)&pxr, g_xr);
    cudaGetSymbolAddress((void**)&pb1, g_b1);
    cudaGetSymbolAddress((void**)&pwd, g_wd);
    cudaGetSymbolAddress((void**)&pt,  g_t);

    const int smem1 = S1STAGES * S1H * 2;   // 48 KB
    const int smem2 = STAGES * STG_H * 2;   // 64 KB
    cudaFuncSetAttribute(k_gemm1, cudaFuncAttributeMaxDynamicSharedMemorySize, smem1);
    cudaFuncSetAttribute(k_gemm2, cudaFuncAttributeMaxDynamicSharedMemorySize, smem2);

    k_pred1<<<(PREDH * 32) / 256, 256>>>(x, W1);
    k_pred2<<<(INTER * 32) / 256, 256>>>(W2);
    k_thresh<<<1, 1024>>>();
    k_collect<<<(INTER + 255) / 256, 256>>>();
    k_rank<<<1, 512>>>();
    k_round_x<<<2048, 256>>>(x);
    k_gatherBW<<<NPAD + HIDDEN, 128>>>(Wg, Wu, Wd);

    // fused gate/up: fine-grained tiles [128 x 64] -> g_t[4096 x 768] (f16, P32)
    dim3 g1(NPAD / 64, SEQ / 128);
    k_gemm1<<<g1, 128, smem1>>>(pxr, pb1, pt);
    // down: out[4096 x 4096] = t @ wd^T  (f32 out); K truncated to 736 —
    // t cols 736..767 are exact zeros, so dropping them is bit-identical.
    dim3 g2(HIDDEN / 128, SEQ / 128);
    k_gemm2<<<g2, 256, smem2>>>(pt, pwd, out, KDOWN, KPAD, KPAD, HIDDEN);
}

// round 17
// speedup vs baseline: 1.1983x; 1.1983x over previous
#include <cuda_runtime.h>
#include <cuda_fp16.h>
#include <cstdint>

#define HIDDEN 4096
#define INTER  14336
#define PREDH  1024
#define SEQ    4096
#define HC     716
#define NPAD   1536   // interleaved gate/up rows, padded
#define KPAD   768    // t / Wd storage stride
#define KDOWN  736    // down-GEMM K loop bound (= 23*32; cols 716..735 are exact zeros)
#define NBINS  4096

// ---------------- device scratch ----------------
__device__ __align__(256) float    g_p[PREDH];
__device__ __align__(256) unsigned g_key[INTER];
__device__ int g_hist[NBINS];
__device__ int g_cnt[4];
__device__ int g_sel[2];
__device__ __align__(256) int g_idx[HC];
__device__ int      g_cand_idx[INTER];
__device__ unsigned g_cand_key[INTER];
__device__ __align__(1024) __half g_xr[(size_t)SEQ * HIDDEN];   // x, f16, k-permuted
__device__ __align__(1024) __half g_b1[(size_t)NPAD * HIDDEN];  // interleaved Wg/Wu, f16, permuted
__device__ __align__(1024) __half g_wd[(size_t)HIDDEN * KPAD];  // gathered Wd, f16, permuted
__device__ __align__(1024) __half g_t [(size_t)SEQ * KPAD];     // silu(g)*u, f16, permuted

// ---------------- helpers ----------------
__device__ __forceinline__ unsigned smem_u32(const void* p) {
    return (unsigned)__cvta_generic_to_shared(p);
}
__device__ __forceinline__ void cp16(unsigned dst, const void* src) {
    asm volatile("cp.async.cg.shared.global [%0], [%1], 16;" :: "r"(dst), "l"(src) : "memory");
}
__device__ __forceinline__ void mmaf16(float* d, unsigned a0, unsigned a1, unsigned a2,
                                       unsigned a3, unsigned b0, unsigned b1) {
    asm volatile(
        "mma.sync.aligned.m16n8k16.row.col.f32.f16.f16.f32 "
        "{%0,%1,%2,%3}, {%4,%5,%6,%7}, {%8,%9}, {%0,%1,%2,%3};\n"
        : "+f"(d[0]), "+f"(d[1]), "+f"(d[2]), "+f"(d[3])
        : "r"(a0), "r"(a1), "r"(a2), "r"(a3), "r"(b0), "r"(b1));
}

// P32 permutation: within each 32-k block, pos = c*8 + b*4 + hi*2 + lo
// where k = 16*b + 8*hi + 2*c + lo.
__device__ __forceinline__ void perm_store32(const float* v, __half* dst) {
#pragma unroll
    for (int pos = 0; pos < 32; pos += 2) {
        int c = pos >> 3, b = (pos >> 2) & 1, hi = (pos >> 1) & 1;
        int k0 = 16 * b + 8 * hi + 2 * c;
        *(__half2*)(dst + pos) = __floats2half2_rn(v[k0], v[k0 + 1]);
    }
}

// ---------------- predictor (init fused) ----------------
__global__ void k_pred1(const float* __restrict__ x, const float* __restrict__ W1) {
    int gid = blockIdx.x * blockDim.x + threadIdx.x;
    if (gid < NBINS) g_hist[gid] = 0;
    if (gid < 4) g_cnt[gid] = 0;
    const float* xl = x + (size_t)(SEQ - 1) * HIDDEN;
    int warp = gid >> 5;
    int lane = threadIdx.x & 31;
    if (warp >= PREDH) return;
    const float* w = W1 + (size_t)warp * HIDDEN;
    double s = 0.0;
    for (int k = lane; k < HIDDEN; k += 32) s += (double)w[k] * (double)xl[k];
    for (int o = 16; o; o >>= 1) s += __shfl_down_sync(0xffffffffu, s, o);
    if (lane == 0) g_p[warp] = (float)s;
}
__global__ void k_pred2(const float* __restrict__ W2) {
    int warp = (blockIdx.x * blockDim.x + threadIdx.x) >> 5;
    int lane = threadIdx.x & 31;
    if (warp >= INTER) return;
    const float* w = W2 + (size_t)warp * PREDH;
    double s = 0.0;
    for (int k = lane; k < PREDH; k += 32) s += (double)w[k] * (double)g_p[k];
    for (int o = 16; o; o >>= 1) s += __shfl_down_sync(0xffffffffu, s, o);
    if (lane == 0) {
        float v = (float)s;
        unsigned u = __float_as_uint(v);
        u = (u & 0x80000000u) ? ~u : (u | 0x80000000u);
        g_key[warp] = u;
        atomicAdd(&g_hist[u >> 20], 1);
    }
}

// ---------------- threshold bin (1 block) ----------------
__global__ void k_thresh() {
    __shared__ int s4[1024];
    __shared__ int gsum[32];
    __shared__ int gabove[32];
    int t = threadIdx.x;
    s4[t] = g_hist[4*t] + g_hist[4*t+1] + g_hist[4*t+2] + g_hist[4*t+3];
    __syncthreads();
    if (t < 32) {
        int s = 0;
        for (int j = 0; j < 32; ++j) s += s4[t * 32 + j];
        gsum[t] = s;
    }
    __syncthreads();
    if (t == 0) {
        int acc = 0;
        for (int g = 31; g >= 0; --g) { gabove[g] = acc; acc += gsum[g]; }
        int g = 31;
        while (gabove[g] + gsum[g] < HC) --g;
        acc = gabove[g];
        for (int c = 31; c >= 0; --c) {
            int cell = g * 32 + c;
            int sc = s4[cell];
            if (acc + sc >= HC) {
                for (int bb = 3; bb >= 0; --bb) {
                    int h = g_hist[cell * 4 + bb];
                    if (acc + h >= HC) { g_sel[0] = cell * 4 + bb; g_sel[1] = acc; return; }
                    acc += h;
                }
            }
            acc += sc;
        }
    }
}
// ---------------- collect (multi-block, parallel scan of keys) -------------
__global__ void k_collect() {
    int i = blockIdx.x * blockDim.x + threadIdx.x;
    if (i >= INTER) return;
    unsigned key = g_key[i];
    int bin = g_sel[0];
    int b = (int)(key >> 20);
    if (b > bin) {
        int p = atomicAdd(&g_cnt[0], 1);
        g_idx[p] = i;
    } else if (b == bin) {
        int p = atomicAdd(&g_cnt[1], 1);
        g_cand_idx[p] = i;
        g_cand_key[p] = key;
    }
}
// ---------------- rank boundary bin (1 block) ----------------
__global__ void k_rank() {
    __shared__ unsigned sk[4096];
    __shared__ int      si[4096];
    int t = threadIdx.x;
    int m = g_cnt[1];
    int above = g_sel[1];
    int need = HC - above;
    bool use_s = (m <= 4096);
    if (use_s)
        for (int i = t; i < m; i += 512) { sk[i] = g_cand_key[i]; si[i] = g_cand_idx[i]; }
    __syncthreads();
    for (int j = t; j < m; j += 512) {
        unsigned kj = use_s ? sk[j] : g_cand_key[j];
        int ij      = use_s ? si[j] : g_cand_idx[j];
        int r = 0;
        for (int l = 0; l < m; ++l) {
            unsigned kl = use_s ? sk[l] : g_cand_key[l];
            int il      = use_s ? si[l] : g_cand_idx[l];
            r += (int)((kl > kj) || (kl == kj && il < ij));
        }
        if (r < need) g_idx[above + r] = ij;
    }
}

// ---------------- staging ----------------
__global__ void k_round_x(const float* __restrict__ x) {
    int nb = SEQ * HIDDEN / 32;
    for (int b = blockIdx.x * blockDim.x + threadIdx.x; b < nb; b += gridDim.x * blockDim.x) {
        float v[32];
        const float4* s = (const float4*)(x + (size_t)b * 32);
#pragma unroll
        for (int q = 0; q < 8; ++q) {
            float4 f = s[q];
            v[q*4] = f.x; v[q*4+1] = f.y; v[q*4+2] = f.z; v[q*4+3] = f.w;
        }
        perm_store32(v, g_xr + (size_t)b * 32);
    }
}
// blocks [0,NPAD): interleaved Wg/Wu row gather.  blocks [NPAD, NPAD+HIDDEN): Wd gather.
__global__ void k_gatherBW(const float* __restrict__ Wg, const float* __restrict__ Wu,
                           const float* __restrict__ Wd) {
    int bid = blockIdx.x;
    int t = threadIdx.x;
    if (bid < NPAD) {
        int k = bid >> 1;
        __half* dst = g_b1 + (size_t)bid * HIDDEN;
        if (k < HC) {
            const float* src = ((bid & 1) ? Wu : Wg) + (size_t)__ldg(&g_idx[k]) * HIDDEN;
            float v[32];
            const float4* s = (const float4*)(src + t * 32);
#pragma unroll
            for (int q = 0; q < 8; ++q) {
                float4 f = s[q];
                v[q*4] = f.x; v[q*4+1] = f.y; v[q*4+2] = f.z; v[q*4+3] = f.w;
            }
            perm_store32(v, dst + t * 32);
        } else {
            uint4* d4 = (uint4*)dst;
            for (int j = t * 4; j < (int)(HIDDEN * 2 / 16); j += 512) {
                d4[j] = make_uint4(0,0,0,0); d4[j+1] = make_uint4(0,0,0,0);
                d4[j+2] = make_uint4(0,0,0,0); d4[j+3] = make_uint4(0,0,0,0);
            }
        }
    } else {
        int h = bid - NPAD;
        if (t >= KPAD / 32) return;
        const float* row = Wd + (size_t)h * INTER;
        float v[32];
#pragma unroll
        for (int j = 0; j < 32; ++j) {
            int k = t * 32 + j;
            v[j] = (k < HC) ? __ldg(row + __ldg(&g_idx[k])) : 0.f;
        }
        perm_store32(v, g_wd + (size_t)h * KPAD + t * 32);
    }
}

// ---------------- f16 mma GEMM (R6 config, byte-exact): 256 thr, 64x32 warp
// tile, BK=32, 4 stages, prefetch-before-wait, 2 barriers/iter --------------
#define STAGES 4
#define STG_H  8192            // halves per stage: A 4096 + B 4096 (16 KB)

__global__ void __launch_bounds__(256, 2) k_gemm2(
    const __half* __restrict__ A, const __half* __restrict__ B,
    void* __restrict__ Cv, int K, int lda, int ldb, int ldc, int epi)
{
    extern __shared__ __half dsm[];
    unsigned smb = smem_u32(dsm);

    int tid = threadIdx.x;
    int lane = tid & 31;
    int warp = tid >> 5;
    int wm = warp >> 2;   // 0..1
    int wn = warp & 3;    // 0..3
    int bm = blockIdx.y * 128;
    int bn = blockIdx.x * 128;

    int lrow = tid >> 1;
    int lpart = tid & 1;
    const __half* asrc = A + (size_t)(bm + lrow) * lda + lpart * 16;
    const __half* bsrc = B + (size_t)(bn + lrow) * ldb + lpart * 16;
    unsigned aoff = (unsigned)(lrow * 64 + lpart * 32);
    unsigned boff = 8192u + aoff;

    float acc[4][4][4];
#pragma unroll
    for (int i = 0; i < 4; i++)
#pragma unroll
        for (int j = 0; j < 4; j++)
#pragma unroll
            for (int q = 0; q < 4; q++) acc[i][j][q] = 0.f;

    int NT = K / 32;
    auto load = [&](int kt) {
        unsigned base = smb + (unsigned)(kt & (STAGES - 1)) * (STG_H * 2u);
        int k0 = kt * 32;
        cp16(base + aoff,       asrc + k0);
        cp16(base + aoff + 16u, asrc + k0 + 8);
        cp16(base + boff,       bsrc + k0);
        cp16(base + boff + 16u, bsrc + k0 + 8);
        asm volatile("cp.async.commit_group;" ::: "memory");
    };

    load(0);
    if (NT > 1) load(1);
    if (NT > 2) load(2);

    int r4 = lane >> 2, c4 = lane & 3;

    for (int kt = 0; kt < NT; ++kt) {
        if (kt + 3 < NT) load(kt + 3);
        int rem = NT - 1 - kt;
        if (rem >= 3)      asm volatile("cp.async.wait_group 3;" ::: "memory");
        else if (rem == 2) asm volatile("cp.async.wait_group 2;" ::: "memory");
        else if (rem == 1) asm volatile("cp.async.wait_group 1;" ::: "memory");
        else               asm volatile("cp.async.wait_group 0;" ::: "memory");
        __syncthreads();

        const uint4* as = (const uint4*)(dsm + (size_t)(kt & (STAGES - 1)) * STG_H);
        const uint4* bs = as + 512;   // B half at +4096 halves = +512 uint4

        uint4 vb[4];
#pragma unroll
        for (int ni = 0; ni < 4; ++ni)
            vb[ni] = bs[(wn * 32 + ni * 8 + r4) * 4 + c4];

#pragma unroll
        for (int mi = 0; mi < 4; ++mi) {
            int rbase = wm * 64 + mi * 16 + r4;
            uint4 va0 = as[rbase * 4 + c4];
            uint4 va1 = as[(rbase + 8) * 4 + c4];
#pragma unroll
            for (int ni = 0; ni < 4; ++ni) {
                mmaf16(acc[mi][ni], va0.x, va1.x, va0.y, va1.y, vb[ni].x, vb[ni].y);
                mmaf16(acc[mi][ni], va0.z, va1.z, va0.w, va1.w, vb[ni].z, vb[ni].w);
            }
        }
        __syncthreads();
    }

    if (epi == 1) {
        __half* Ct = (__half*)Cv;
        __half* ts = dsm;
        const int TST = 72;
        int jblk = (wn >> 1) * 32;
        int bsel = (wn & 1) * 4;
#pragma unroll
        for (int mi = 0; mi < 4; ++mi) {
            int rl = wm * 64 + mi * 16 + r4;
#pragma unroll
            for (int ni = 0; ni < 4; ++ni) {
                int q = ni * 4 + c4;
                int ppos = jblk + ((q & 7) >> 1) * 8 + bsel + (q >> 3) * 2 + (c4 & 1);
                float g0 = acc[mi][ni][0], u0 = acc[mi][ni][1];
                float g1 = acc[mi][ni][2], u1 = acc[mi][ni][3];
                ts[rl * TST + ppos]       = __float2half(u0 * g0 / (1.f + __expf(-g0)));
                ts[(rl + 8) * TST + ppos] = __float2half(u1 * g1 / (1.f + __expf(-g1)));
            }
        }
        __syncthreads();
        int row = tid >> 1, hsel = tid & 1;
        const uint4* src = (const uint4*)(ts + row * TST + hsel * 32);
        uint4* dst = (uint4*)(Ct + (size_t)(bm + row) * ldc + (bn >> 1) + hsel * 32);
#pragma unroll
        for (int c = 0; c < 4; ++c) dst[c] = src[c];
    } else {
        float* C = (float*)Cv;
#pragma unroll
        for (int mi = 0; mi < 4; ++mi) {
            int r0 = bm + wm * 64 + mi * 16 + r4;
#pragma unroll
            for (int ni = 0; ni < 4; ++ni) {
                int cc = bn + wn * 32 + ni * 8 + c4 * 2;
                *(float2*)&C[(size_t)r0 * ldc + cc] =
                    make_float2(acc[mi][ni][0], acc[mi][ni][1]);
                *(float2*)&C[(size_t)(r0 + 8) * ldc + cc] =
                    make_float2(acc[mi][ni][2], acc[mi][ni][3]);
            }
        }
    }
}

// ---------------- launch (single stream, fully sequential) ----------------
extern "C" void kernel_launch(void* const* d_in, const int* in_sizes, int n_in,
                              void* d_out, int out_size) {
    (void)in_sizes; (void)n_in; (void)out_size;
    const float* x  = (const float*)d_in[0];
    const float* Wg = (const float*)d_in[1];
    const float* Wu = (const float*)d_in[2];
    const float* Wd = (const float*)d_in[3];
    const float* W1 = (const float*)d_in[4];
    const float* W2 = (const float*)d_in[5];
    float* out = (float*)d_out;

    __half *pxr = nullptr, *pb1 = nullptr, *pwd = nullptr, *pt = nullptr;
    cudaGetSymbolAddress((void**)&pxr, g_xr);
    cudaGetSymbolAddress((void**)&pb1, g_b1);
    cudaGetSymbolAddress((void**)&pwd, g_wd);
    cudaGetSymbolAddress((void**)&pt,  g_t);

    const int smem_bytes = STAGES * STG_H * 2;   // 64 KB
    cudaFuncSetAttribute(k_gemm2, cudaFuncAttributeMaxDynamicSharedMemorySize, smem_bytes);

    k_pred1<<<(PREDH * 32) / 256, 256>>>(x, W1);
    k_pred2<<<(INTER * 32) / 256, 256>>>(W2);
    k_thresh<<<1, 1024>>>();
    k_collect<<<(INTER + 255) / 256, 256>>>();
    k_rank<<<1, 512>>>();
    k_round_x<<<2048, 256>>>(x);
    k_gatherBW<<<NPAD + HIDDEN, 128>>>(Wg, Wu, Wd);

    // fused gate/up: [4096 x 1536] -> g_t[4096 x 768] (f16, permuted)
    dim3 g1(NPAD / 128, SEQ / 128);
    k_gemm2<<<g1, 256, smem_bytes>>>(pxr, pb1, pt, HIDDEN, HIDDEN, HIDDEN, KPAD, 1);
    // down: out[4096 x 4096] = t @ wd^T  (f32 out); K truncated to 736 —
    // t cols 736..767 are exact zeros, so dropping them is bit-identical.
    dim3 g2(HIDDEN / 128, SEQ / 128);
    k_gemm2<<<g2, 256, smem_bytes>>>(pt, pwd, out, KDOWN, KPAD, KPAD, HIDDEN, 0);
}